// round 4
// baseline (speedup 1.0000x reference)
#include <cuda_runtime.h>
#include <cuda_bf16.h>
#include <cstdint>

// Problem constants (fixed shapes)
#define NN      50000
#define EE      800000
#define IN_C    64
#define EDGE_C  32
#define OUT_C   64
#define TILE_E  128                  // sorted edges per block-tile
#define N_TILES (EE / TILE_E)        // 6250 exactly
#define NB_SCAN 196                  // ceil(50000/256)

// Scratch (device globals; no runtime allocation allowed)
__device__ __align__(16) float g_A[NN * OUT_C];   // x @ W1[0:64]
__device__ __align__(16) float g_B[NN * OUT_C];   // x @ W1[64:128]
__device__ __align__(16) float g_H[NN * OUT_C];   // scatter-sum of relu(h)
__device__ int g_deg[NN];            // in-degree
__device__ int g_start[NN];          // exclusive prefix of deg
__device__ int g_cursor[NN];         // scatter cursors
__device__ int g_bsum[256];          // scan block sums
__device__ int g_boff[256];          // scanned block offsets
__device__ int g_seid[EE];           // sorted-by-col: original edge id
__device__ int g_scol[EE];           // sorted-by-col: col
__device__ int g_srow[EE];           // sorted-by-col: row

typedef unsigned long long u64;

// ---------------------------------------------------------------------------
// packed fp32x2 helpers
// ---------------------------------------------------------------------------
__device__ __forceinline__ u64 pack2(float lo, float hi) {
    u64 r; asm("mov.b64 %0, {%1, %2};" : "=l"(r) : "f"(lo), "f"(hi)); return r;
}
__device__ __forceinline__ u64 dup2(float v) {
    u64 r; asm("mov.b64 %0, {%1, %1};" : "=l"(r) : "f"(v)); return r;
}
__device__ __forceinline__ void fma2(u64& d, u64 a, u64 b) {
    asm("fma.rn.f32x2 %0, %1, %2, %0;" : "+l"(d) : "l"(a), "l"(b));
}
__device__ __forceinline__ float2 unpack2(u64 v) {
    float2 f; asm("mov.b64 {%0, %1}, %2;" : "=f"(f.x), "=f"(f.y) : "l"(v)); return f;
}

// vector reduction-add to global: 1 instruction per 4 floats
__device__ __forceinline__ void red_add_v4(float* p, float4 v) {
    asm volatile("red.global.add.v4.f32 [%0], {%1, %2, %3, %4};"
                 :: "l"(p), "f"(v.x), "f"(v.y), "f"(v.z), "f"(v.w)
                 : "memory");
}

// ---------------------------------------------------------------------------
// Kernel 0: zero H accumulator + degree histogram
// ---------------------------------------------------------------------------
__global__ void zero_kernel() {
    int id = blockIdx.x * blockDim.x + threadIdx.x;
    if (id < (NN * OUT_C) / 4) {
        reinterpret_cast<float4*>(g_H)[id] = make_float4(0.f, 0.f, 0.f, 0.f);
    }
    if (id < NN) g_deg[id] = 0;
}

// ---------------------------------------------------------------------------
// Kernel 1: per-node precompute  A = x @ W1a,  B = x @ W1b
// ---------------------------------------------------------------------------
__global__ __launch_bounds__(256)
void pre_kernel(const float* __restrict__ x, const float* __restrict__ W1) {
    __shared__ float Wa_s[IN_C * OUT_C];
    __shared__ float Wb_s[IN_C * OUT_C];
    __shared__ float x_s[64 * IN_C];

    int t = threadIdx.x;
    for (int i = t; i < IN_C * OUT_C; i += 256) {
        Wa_s[i] = W1[i];
        Wb_s[i] = W1[IN_C * OUT_C + i];
    }

    const int tc = t & 15;
    const int tn = t >> 4;
    const int base = blockIdx.x * 64;
    {
        const float4* x4 = reinterpret_cast<const float4*>(x);
        float4* xs4 = reinterpret_cast<float4*>(x_s);
        #pragma unroll
        for (int i = 0; i < 4; i++) {
            int id = t + 256 * i;
            int n = id >> 4, q = id & 15;
            int gn = base + n;
            float4 v = make_float4(0.f, 0.f, 0.f, 0.f);
            if (gn < NN) v = x4[gn * 16 + q];
            xs4[n * 16 + q] = v;
        }
    }
    __syncthreads();

    u64 aAL[4], aAH[4], aBL[4], aBH[4];
    #pragma unroll
    for (int n = 0; n < 4; n++) { aAL[n] = 0; aAH[n] = 0; aBL[n] = 0; aBH[n] = 0; }

    const ulonglong2* wa2 = reinterpret_cast<const ulonglong2*>(Wa_s);
    const ulonglong2* wb2 = reinterpret_cast<const ulonglong2*>(Wb_s);
    const float4* xs4 = reinterpret_cast<const float4*>(x_s);

    #pragma unroll
    for (int kb = 0; kb < IN_C / 4; kb++) {
        ulonglong2 wa[4], wb[4];
        #pragma unroll
        for (int kk = 0; kk < 4; kk++) {
            wa[kk] = wa2[(4 * kb + kk) * 16 + tc];
            wb[kk] = wb2[(4 * kb + kk) * 16 + tc];
        }
        #pragma unroll
        for (int n = 0; n < 4; n++) {
            float4 v4 = xs4[(4 * tn + n) * 16 + kb];
            u64 d0 = dup2(v4.x), d1 = dup2(v4.y), d2 = dup2(v4.z), d3 = dup2(v4.w);
            fma2(aAL[n], d0, wa[0].x); fma2(aAH[n], d0, wa[0].y);
            fma2(aBL[n], d0, wb[0].x); fma2(aBH[n], d0, wb[0].y);
            fma2(aAL[n], d1, wa[1].x); fma2(aAH[n], d1, wa[1].y);
            fma2(aBL[n], d1, wb[1].x); fma2(aBH[n], d1, wb[1].y);
            fma2(aAL[n], d2, wa[2].x); fma2(aAH[n], d2, wa[2].y);
            fma2(aBL[n], d2, wb[2].x); fma2(aBH[n], d2, wb[2].y);
            fma2(aAL[n], d3, wa[3].x); fma2(aAH[n], d3, wa[3].y);
            fma2(aBL[n], d3, wb[3].x); fma2(aBH[n], d3, wb[3].y);
        }
    }

    float4* A4 = reinterpret_cast<float4*>(g_A);
    float4* B4 = reinterpret_cast<float4*>(g_B);
    #pragma unroll
    for (int n = 0; n < 4; n++) {
        int gn = base + 4 * tn + n;
        if (gn < NN) {
            float2 al = unpack2(aAL[n]), ah = unpack2(aAH[n]);
            float2 bl = unpack2(aBL[n]), bh = unpack2(aBH[n]);
            A4[gn * 16 + tc] = make_float4(al.x, al.y, ah.x, ah.y);
            B4[gn * 16 + tc] = make_float4(bl.x, bl.y, bh.x, bh.y);
        }
    }
}

// ---------------------------------------------------------------------------
// Sort pipeline: histogram -> scan (3 stages) -> scatter
// ---------------------------------------------------------------------------
__global__ void hist_kernel(const int* __restrict__ col) {
    int e = blockIdx.x * blockDim.x + threadIdx.x;
    if (e < EE) atomicAdd(&g_deg[col[e]], 1);
}

__global__ void scan1_kernel() {
    __shared__ int s[256];
    const int t = threadIdx.x;
    const int i = blockIdx.x * 256 + t;
    int v = (i < NN) ? g_deg[i] : 0;
    s[t] = v;
    __syncthreads();
    #pragma unroll
    for (int off = 1; off < 256; off <<= 1) {
        int x = (t >= off) ? s[t - off] : 0;
        __syncthreads();
        s[t] += x;
        __syncthreads();
    }
    if (i < NN) g_start[i] = s[t] - v;          // exclusive within block
    if (t == 255) g_bsum[blockIdx.x] = s[255];  // block total
}

__global__ void scan2_kernel() {
    __shared__ int s[256];
    const int t = threadIdx.x;
    int v = (t < NB_SCAN) ? g_bsum[t] : 0;
    s[t] = v;
    __syncthreads();
    #pragma unroll
    for (int off = 1; off < 256; off <<= 1) {
        int x = (t >= off) ? s[t - off] : 0;
        __syncthreads();
        s[t] += x;
        __syncthreads();
    }
    g_boff[t] = s[t] - v;                        // exclusive block offsets
}

__global__ void scan3_kernel() {
    const int i = blockIdx.x * 256 + threadIdx.x;
    if (i < NN) {
        int st = g_start[i] + g_boff[blockIdx.x];
        g_start[i] = st;
        g_cursor[i] = st;
    }
}

__global__ void scatter_kernel(const int* __restrict__ row,
                               const int* __restrict__ col) {
    int e = blockIdx.x * blockDim.x + threadIdx.x;
    if (e < EE) {
        int c = col[e];
        int pos = atomicAdd(&g_cursor[c], 1);
        g_seid[pos] = e;
        g_scol[pos] = c;
        g_srow[pos] = row[e];
    }
}

// ---------------------------------------------------------------------------
// Kernel 2: edge kernel over col-sorted edges with run-merged scatter.
// Tile = 128 sorted edges; thread (tc, te): tc = 4 channels, te handles 8
// consecutive edges as two groups of 4. Accumulate relu(h) in registers while
// col stays constant; flush one red.v4 per run boundary.
// ---------------------------------------------------------------------------
__global__ __launch_bounds__(256)
void edge_kernel(const float* __restrict__ ea,
                 const float* __restrict__ W1, const float* __restrict__ b1) {
    __shared__ float Wc_s[EDGE_C * OUT_C];     // 8KB
    __shared__ float ea_s[TILE_E * EDGE_C];    // 16KB
    __shared__ int seid_s[TILE_E];
    __shared__ int scol_s[TILE_E];
    __shared__ int srow_s[TILE_E];

    const int t = threadIdx.x;
    for (int i = t; i < EDGE_C * OUT_C; i += 256) Wc_s[i] = W1[128 * 64 + i];

    const int tc = t & 15;     // channels 4*tc..4*tc+3
    const int te = t >> 4;     // edge group: edges 8*te..8*te+7

    const float4 b1v = *reinterpret_cast<const float4*>(b1 + 4 * tc);

    const ulonglong2* Wc2 = reinterpret_cast<const ulonglong2*>(Wc_s);
    const float4* A4  = reinterpret_cast<const float4*>(g_A);
    const float4* B4  = reinterpret_cast<const float4*>(g_B);
    const float4* ea4s = reinterpret_cast<const float4*>(ea_s);
    const float4* eg4 = reinterpret_cast<const float4*>(ea);

    for (int tile = blockIdx.x; tile < N_TILES; tile += gridDim.x) {
        const int base = tile * TILE_E;

        __syncthreads();   // protect smem from previous iteration readers
        if (t < TILE_E) {
            seid_s[t] = g_seid[base + t];
            scol_s[t] = g_scol[base + t];
            srow_s[t] = g_srow[base + t];
        }
        __syncthreads();
        // stage ea rows (permuted gather, 128B per edge)
        {
            float4* es4 = reinterpret_cast<float4*>(ea_s);
            #pragma unroll
            for (int i = 0; i < 4; i++) {
                int id = t + 256 * i;          // 0..1023
                int e = id >> 3, q = id & 7;
                es4[id] = eg4[(size_t)seid_s[e] * 8 + q];
            }
        }
        __syncthreads();

        int runc = -1;
        float4 racc = make_float4(0.f, 0.f, 0.f, 0.f);

        #pragma unroll
        for (int g = 0; g < 2; g++) {
            const int e0 = 8 * te + 4 * g;

            // ---- layer 1 for 4 edges: acc = A[row] + B[col] + b1 + ea @ Wc
            u64 accL[4], accH[4];
            int cdst[4];
            #pragma unroll
            for (int e = 0; e < 4; e++) {
                const int ed = e0 + e;
                const int r = srow_s[ed], c = scol_s[ed];
                cdst[e] = c;
                float4 a = A4[r * 16 + tc];
                float4 b = B4[c * 16 + tc];
                accL[e] = pack2(a.x + b.x + b1v.x, a.y + b.y + b1v.y);
                accH[e] = pack2(a.z + b.z + b1v.z, a.w + b.w + b1v.w);
            }
            #pragma unroll
            for (int kb = 0; kb < EDGE_C / 4; kb++) {
                ulonglong2 w[4];
                #pragma unroll
                for (int kk = 0; kk < 4; kk++) w[kk] = Wc2[(4 * kb + kk) * 16 + tc];
                #pragma unroll
                for (int e = 0; e < 4; e++) {
                    float4 v4 = ea4s[(e0 + e) * 8 + kb];
                    u64 d0 = dup2(v4.x), d1 = dup2(v4.y), d2 = dup2(v4.z), d3 = dup2(v4.w);
                    fma2(accL[e], d0, w[0].x); fma2(accH[e], d0, w[0].y);
                    fma2(accL[e], d1, w[1].x); fma2(accH[e], d1, w[1].y);
                    fma2(accL[e], d2, w[2].x); fma2(accH[e], d2, w[2].y);
                    fma2(accL[e], d3, w[3].x); fma2(accH[e], d3, w[3].y);
                }
            }

            // ---- relu + run-merge ----
            #pragma unroll
            for (int e = 0; e < 4; e++) {
                float2 lo = unpack2(accL[e]), hi = unpack2(accH[e]);
                float4 h = make_float4(fmaxf(lo.x, 0.f), fmaxf(lo.y, 0.f),
                                       fmaxf(hi.x, 0.f), fmaxf(hi.y, 0.f));
                if (cdst[e] == runc) {
                    racc.x += h.x; racc.y += h.y; racc.z += h.z; racc.w += h.w;
                } else {
                    if (runc >= 0)
                        red_add_v4(g_H + (size_t)runc * OUT_C + 4 * tc, racc);
                    runc = cdst[e];
                    racc = h;
                }
            }
        }
        // final flush for this tile
        if (runc >= 0)
            red_add_v4(g_H + (size_t)runc * OUT_C + 4 * tc, racc);
    }
}

// ---------------------------------------------------------------------------
// Kernel 3: node GEMM + mean + bias:  out = (H @ W2) / max(deg,1) + b2
//           (zero-degree nodes output exactly 0, matching reference)
// ---------------------------------------------------------------------------
__global__ __launch_bounds__(256)
void out_kernel(const float* __restrict__ W2, const float* __restrict__ b2,
                float* __restrict__ out) {
    __shared__ float W2_s[OUT_C * OUT_C];
    __shared__ float h_s[64 * OUT_C];

    const int t = threadIdx.x;
    for (int i = t; i < OUT_C * OUT_C; i += 256) W2_s[i] = W2[i];

    const int tc = t & 15;
    const int tn = t >> 4;
    const int base = blockIdx.x * 64;
    {
        const float4* H4 = reinterpret_cast<const float4*>(g_H);
        float4* hs4 = reinterpret_cast<float4*>(h_s);
        #pragma unroll
        for (int i = 0; i < 4; i++) {
            int id = t + 256 * i;
            int n = id >> 4, q = id & 15;
            int gn = base + n;
            float4 v = make_float4(0.f, 0.f, 0.f, 0.f);
            if (gn < NN) v = H4[gn * 16 + q];
            hs4[n * 16 + q] = v;
        }
    }
    __syncthreads();

    u64 aL[4], aH[4];
    #pragma unroll
    for (int n = 0; n < 4; n++) { aL[n] = 0; aH[n] = 0; }

    const ulonglong2* w2 = reinterpret_cast<const ulonglong2*>(W2_s);
    const float4* hs4 = reinterpret_cast<const float4*>(h_s);

    #pragma unroll
    for (int kb = 0; kb < OUT_C / 4; kb++) {
        ulonglong2 w[4];
        #pragma unroll
        for (int kk = 0; kk < 4; kk++) w[kk] = w2[(4 * kb + kk) * 16 + tc];
        #pragma unroll
        for (int n = 0; n < 4; n++) {
            float4 v4 = hs4[(4 * tn + n) * 16 + kb];
            u64 d0 = dup2(v4.x), d1 = dup2(v4.y), d2 = dup2(v4.z), d3 = dup2(v4.w);
            fma2(aL[n], d0, w[0].x); fma2(aH[n], d0, w[0].y);
            fma2(aL[n], d1, w[1].x); fma2(aH[n], d1, w[1].y);
            fma2(aL[n], d2, w[2].x); fma2(aH[n], d2, w[2].y);
            fma2(aL[n], d3, w[3].x); fma2(aH[n], d3, w[3].y);
        }
    }

    const float4 b2v = *reinterpret_cast<const float4*>(b2 + 4 * tc);
    float4* out4 = reinterpret_cast<float4*>(out);
    #pragma unroll
    for (int n = 0; n < 4; n++) {
        int gn = base + 4 * tn + n;
        if (gn < NN) {
            int d = g_deg[gn];
            float2 lo = unpack2(aL[n]), hi = unpack2(aH[n]);
            float4 o;
            if (d == 0) {
                o = make_float4(0.f, 0.f, 0.f, 0.f);
            } else {
                float inv = 1.0f / (float)d;
                o = make_float4(lo.x * inv + b2v.x, lo.y * inv + b2v.y,
                                hi.x * inv + b2v.z, hi.y * inv + b2v.w);
            }
            out4[gn * 16 + tc] = o;
        }
    }
}

// ---------------------------------------------------------------------------
// Launch
// ---------------------------------------------------------------------------
extern "C" void kernel_launch(void* const* d_in, const int* in_sizes, int n_in,
                              void* d_out, int out_size) {
    const float* x    = (const float*)d_in[0];
    const int*   eidx = (const int*)d_in[1];     // [2][E]: row then col
    const float* ea   = (const float*)d_in[2];
    const float* W1   = (const float*)d_in[3];
    const float* b1   = (const float*)d_in[4];
    const float* W2   = (const float*)d_in[5];
    const float* b2   = (const float*)d_in[6];
    float* out = (float*)d_out;

    const int* row = eidx;
    const int* col = eidx + EE;

    // 0) zero H + degree
    {
        int total = (NN * OUT_C) / 4;
        zero_kernel<<<(total + 255) / 256, 256>>>();
    }
    // 1) per-node projections A, B (overlap-independent of sort pipeline)
    pre_kernel<<<(NN + 63) / 64, 256>>>(x, W1);
    // 2) counting sort by col
    hist_kernel<<<(EE + 255) / 256, 256>>>(col);
    scan1_kernel<<<NB_SCAN, 256>>>();
    scan2_kernel<<<1, 256>>>();
    scan3_kernel<<<NB_SCAN, 256>>>();
    scatter_kernel<<<(EE + 255) / 256, 256>>>(row, col);
    // 3) edge layer-1 + run-merged scatter
    edge_kernel<<<1184, 256>>>(ea, W1, b1);
    // 4) node GEMM + mean + bias
    out_kernel<<<(NN + 63) / 64, 256>>>(W2, b2, out);
}

// round 5
// speedup vs baseline: 1.6934x; 1.6934x over previous
#include <cuda_runtime.h>
#include <cuda_bf16.h>
#include <cstdint>

// Problem constants (fixed shapes)
#define NN      50000
#define EE      800000
#define IN_C    64
#define EDGE_C  32
#define OUT_C   64
#define TILE_E  64
#define N_TILES (EE / TILE_E)   // 12500 exactly

// Scratch (device globals; 16B-aligned for v4 access)
__device__ __align__(16) float g_A[NN * OUT_C];   // x @ W1[0:64]
__device__ __align__(16) float g_B[NN * OUT_C];   // x @ W1[64:128]
__device__ __align__(16) float g_H[NN * OUT_C];   // scatter-sum of relu(h)
__device__ int g_deg[NN];                          // in-degree

typedef unsigned long long u64;

// ---------------------------------------------------------------------------
// packed fp32x2 helpers
// ---------------------------------------------------------------------------
__device__ __forceinline__ u64 pack2(float lo, float hi) {
    u64 r; asm("mov.b64 %0, {%1, %2};" : "=l"(r) : "f"(lo), "f"(hi)); return r;
}
__device__ __forceinline__ u64 dup2(float v) {
    u64 r; asm("mov.b64 %0, {%1, %1};" : "=l"(r) : "f"(v)); return r;
}
__device__ __forceinline__ void fma2(u64& d, u64 a, u64 b) {
    asm("fma.rn.f32x2 %0, %1, %2, %0;" : "+l"(d) : "l"(a), "l"(b));
}
__device__ __forceinline__ float2 unpack2(u64 v) {
    float2 f; asm("mov.b64 {%0, %1}, %2;" : "=f"(f.x), "=f"(f.y) : "l"(v)); return f;
}

// vector reduction-add to global: 1 instruction per 4 floats
__device__ __forceinline__ void red_add_v4(float* p, float4 v) {
    asm volatile("red.global.add.v4.f32 [%0], {%1, %2, %3, %4};"
                 :: "l"(p), "f"(v.x), "f"(v.y), "f"(v.z), "f"(v.w)
                 : "memory");
}

// ---------------------------------------------------------------------------
// Kernel 0: zero H accumulator + degrees
// ---------------------------------------------------------------------------
__global__ void zero_kernel() {
    int id = blockIdx.x * blockDim.x + threadIdx.x;
    if (id < (NN * OUT_C) / 4) {
        reinterpret_cast<float4*>(g_H)[id] = make_float4(0.f, 0.f, 0.f, 0.f);
    }
    if (id < NN) g_deg[id] = 0;
}

// ---------------------------------------------------------------------------
// Kernel 0b: degree histogram (int atomics, off the hot kernel)
// ---------------------------------------------------------------------------
__global__ void hist_kernel(const int* __restrict__ col) {
    int e = blockIdx.x * blockDim.x + threadIdx.x;
    if (e < EE) atomicAdd(&g_deg[col[e]], 1);
}

// ---------------------------------------------------------------------------
// Kernel 1: per-node precompute  A = x @ W1a,  B = x @ W1b
// Block: 256 threads, tile = 64 nodes. Thread: 4 channels (tc) x 4 nodes (tn).
// ---------------------------------------------------------------------------
__global__ __launch_bounds__(256)
void pre_kernel(const float* __restrict__ x, const float* __restrict__ W1) {
    __shared__ float Wa_s[IN_C * OUT_C];
    __shared__ float Wb_s[IN_C * OUT_C];
    __shared__ float x_s[64 * IN_C];

    int t = threadIdx.x;
    for (int i = t; i < IN_C * OUT_C; i += 256) {
        Wa_s[i] = W1[i];                    // rows 0..63
        Wb_s[i] = W1[IN_C * OUT_C + i];     // rows 64..127
    }

    const int tc = t & 15;
    const int tn = t >> 4;
    const int base = blockIdx.x * 64;
    {
        const float4* x4 = reinterpret_cast<const float4*>(x);
        float4* xs4 = reinterpret_cast<float4*>(x_s);
        #pragma unroll
        for (int i = 0; i < 4; i++) {
            int id = t + 256 * i;
            int n = id >> 4, q = id & 15;
            int gn = base + n;
            float4 v = make_float4(0.f, 0.f, 0.f, 0.f);
            if (gn < NN) v = x4[gn * 16 + q];
            xs4[n * 16 + q] = v;
        }
    }
    __syncthreads();

    u64 aAL[4], aAH[4], aBL[4], aBH[4];
    #pragma unroll
    for (int n = 0; n < 4; n++) { aAL[n] = 0; aAH[n] = 0; aBL[n] = 0; aBH[n] = 0; }

    const ulonglong2* wa2 = reinterpret_cast<const ulonglong2*>(Wa_s);
    const ulonglong2* wb2 = reinterpret_cast<const ulonglong2*>(Wb_s);
    const float4* xs4 = reinterpret_cast<const float4*>(x_s);

    #pragma unroll
    for (int kb = 0; kb < IN_C / 4; kb++) {
        ulonglong2 wa[4], wb[4];
        #pragma unroll
        for (int kk = 0; kk < 4; kk++) {
            wa[kk] = wa2[(4 * kb + kk) * 16 + tc];
            wb[kk] = wb2[(4 * kb + kk) * 16 + tc];
        }
        #pragma unroll
        for (int n = 0; n < 4; n++) {
            float4 v4 = xs4[(4 * tn + n) * 16 + kb];
            u64 d0 = dup2(v4.x), d1 = dup2(v4.y), d2 = dup2(v4.z), d3 = dup2(v4.w);
            fma2(aAL[n], d0, wa[0].x); fma2(aAH[n], d0, wa[0].y);
            fma2(aBL[n], d0, wb[0].x); fma2(aBH[n], d0, wb[0].y);
            fma2(aAL[n], d1, wa[1].x); fma2(aAH[n], d1, wa[1].y);
            fma2(aBL[n], d1, wb[1].x); fma2(aBH[n], d1, wb[1].y);
            fma2(aAL[n], d2, wa[2].x); fma2(aAH[n], d2, wa[2].y);
            fma2(aBL[n], d2, wb[2].x); fma2(aBH[n], d2, wb[2].y);
            fma2(aAL[n], d3, wa[3].x); fma2(aAH[n], d3, wa[3].y);
            fma2(aBL[n], d3, wb[3].x); fma2(aBH[n], d3, wb[3].y);
        }
    }

    float4* A4 = reinterpret_cast<float4*>(g_A);
    float4* B4 = reinterpret_cast<float4*>(g_B);
    #pragma unroll
    for (int n = 0; n < 4; n++) {
        int gn = base + 4 * tn + n;
        if (gn < NN) {
            float2 al = unpack2(aAL[n]), ah = unpack2(aAH[n]);
            float2 bl = unpack2(aBL[n]), bh = unpack2(aBH[n]);
            A4[gn * 16 + tc] = make_float4(al.x, al.y, ah.x, ah.y);
            B4[gn * 16 + tc] = make_float4(bl.x, bl.y, bh.x, bh.y);
        }
    }
}

// ---------------------------------------------------------------------------
// Kernel 2: edge kernel (layer 1 only), pre-duplicated ea staging.
// Per tile of 64 edges:
//   h  = relu(A[row] + B[col] + b1 + ea @ W1c)
//   g_H[col] += h  (red.v4)
// smem: Wc(8K) + ea_dup(16K: each scalar stored as (v,v)) + idx(0.5K).
// ---------------------------------------------------------------------------
__global__ __launch_bounds__(256)
void edge_kernel(const int* __restrict__ row, const int* __restrict__ col,
                 const float* __restrict__ ea,
                 const float* __restrict__ W1, const float* __restrict__ b1) {
    __shared__ float Wc_s[EDGE_C * OUT_C];        // 8KB
    __shared__ float ea_s[TILE_E * EDGE_C * 2];   // 16KB, duplicated pairs
    __shared__ int row_s[TILE_E];
    __shared__ int col_s[TILE_E];

    const int t = threadIdx.x;
    for (int i = t; i < EDGE_C * OUT_C; i += 256) Wc_s[i] = W1[128 * 64 + i];

    const int tc = t & 15;     // channels 4*tc..4*tc+3
    const int te = t >> 4;     // edges (within tile) 4*te..4*te+3

    const float4 b1v = *reinterpret_cast<const float4*>(b1 + 4 * tc);

    const ulonglong2* Wc2 = reinterpret_cast<const ulonglong2*>(Wc_s);
    const float4* A4  = reinterpret_cast<const float4*>(g_A);
    const float4* B4  = reinterpret_cast<const float4*>(g_B);
    // duplicated ea: [edge][k-pair] of ulonglong2, 16 pairs-of-2 per edge:
    // entry (edge, kb2) holds k=2*kb2 and k=2*kb2+1, each duplicated.
    const ulonglong2* ea2s = reinterpret_cast<const ulonglong2*>(ea_s);

    for (int tile = blockIdx.x; tile < N_TILES; tile += gridDim.x) {
        const int base = tile * TILE_E;

        __syncthreads();   // protect smem from previous iteration readers
        if (t < 64) { row_s[t] = row[base + t]; col_s[t] = col[base + t]; }
        {
            // coalesced read of 64x32 floats; write duplicated (v,v) pairs
            const float4* eg4 = reinterpret_cast<const float4*>(ea) +
                                (size_t)base * (EDGE_C / 4);
            float4* es4 = reinterpret_cast<float4*>(ea_s);
            #pragma unroll
            for (int i = 0; i < 2; i++) {
                int id = t + 256 * i;           // 0..511 quads
                float4 v = eg4[id];
                // quad id covers k-range [4q, 4q+4) of edge e = id>>3, q = id&7
                es4[2 * id]     = make_float4(v.x, v.x, v.y, v.y);
                es4[2 * id + 1] = make_float4(v.z, v.z, v.w, v.w);
            }
        }
        __syncthreads();

        // acc = A[row] + B[col] + b1 + ea @ W1c
        u64 accL[4], accH[4];
        int cdst[4];
        #pragma unroll
        for (int e = 0; e < 4; e++) {
            const int ed = 4 * te + e;
            const int r = row_s[ed], c = col_s[ed];
            cdst[e] = c;
            float4 a = A4[r * 16 + tc];
            float4 b = B4[c * 16 + tc];
            accL[e] = pack2(a.x + b.x + b1v.x, a.y + b.y + b1v.y);
            accH[e] = pack2(a.z + b.z + b1v.z, a.w + b.w + b1v.w);
        }
        #pragma unroll
        for (int kb = 0; kb < EDGE_C / 4; kb++) {   // 8 blocks of 4 k
            ulonglong2 w[4];
            #pragma unroll
            for (int kk = 0; kk < 4; kk++) w[kk] = Wc2[(4 * kb + kk) * 16 + tc];
            #pragma unroll
            for (int e = 0; e < 4; e++) {
                // two ulonglong2 loads give k0..k3 duplicated (broadcast LDS)
                ulonglong2 d01 = ea2s[(4 * te + e) * 16 + 2 * kb];
                ulonglong2 d23 = ea2s[(4 * te + e) * 16 + 2 * kb + 1];
                fma2(accL[e], d01.x, w[0].x); fma2(accH[e], d01.x, w[0].y);
                fma2(accL[e], d01.y, w[1].x); fma2(accH[e], d01.y, w[1].y);
                fma2(accL[e], d23.x, w[2].x); fma2(accH[e], d23.x, w[2].y);
                fma2(accL[e], d23.y, w[3].x); fma2(accH[e], d23.y, w[3].y);
            }
        }

        // relu + scatter h into g_H[col]
        #pragma unroll
        for (int e = 0; e < 4; e++) {
            float2 lo = unpack2(accL[e]), hi = unpack2(accH[e]);
            float4 h = make_float4(fmaxf(lo.x, 0.f), fmaxf(lo.y, 0.f),
                                   fmaxf(hi.x, 0.f), fmaxf(hi.y, 0.f));
            red_add_v4(g_H + (size_t)cdst[e] * OUT_C + 4 * tc, h);
        }
    }
}

// ---------------------------------------------------------------------------
// Kernel 3: node GEMM + mean + bias:  out = (H @ W2) / max(deg,1) + b2
//           (zero-degree nodes output exactly 0, matching reference)
// ---------------------------------------------------------------------------
__global__ __launch_bounds__(256)
void out_kernel(const float* __restrict__ W2, const float* __restrict__ b2,
                float* __restrict__ out) {
    __shared__ float W2_s[OUT_C * OUT_C];
    __shared__ float h_s[64 * OUT_C];

    const int t = threadIdx.x;
    for (int i = t; i < OUT_C * OUT_C; i += 256) W2_s[i] = W2[i];

    const int tc = t & 15;
    const int tn = t >> 4;
    const int base = blockIdx.x * 64;
    {
        const float4* H4 = reinterpret_cast<const float4*>(g_H);
        float4* hs4 = reinterpret_cast<float4*>(h_s);
        #pragma unroll
        for (int i = 0; i < 4; i++) {
            int id = t + 256 * i;
            int n = id >> 4, q = id & 15;
            int gn = base + n;
            float4 v = make_float4(0.f, 0.f, 0.f, 0.f);
            if (gn < NN) v = H4[gn * 16 + q];
            hs4[n * 16 + q] = v;
        }
    }
    __syncthreads();

    u64 aL[4], aH[4];
    #pragma unroll
    for (int n = 0; n < 4; n++) { aL[n] = 0; aH[n] = 0; }

    const ulonglong2* w2 = reinterpret_cast<const ulonglong2*>(W2_s);
    const float4* hs4 = reinterpret_cast<const float4*>(h_s);

    #pragma unroll
    for (int kb = 0; kb < OUT_C / 4; kb++) {
        ulonglong2 w[4];
        #pragma unroll
        for (int kk = 0; kk < 4; kk++) w[kk] = w2[(4 * kb + kk) * 16 + tc];
        #pragma unroll
        for (int n = 0; n < 4; n++) {
            float4 v4 = hs4[(4 * tn + n) * 16 + kb];
            u64 d0 = dup2(v4.x), d1 = dup2(v4.y), d2 = dup2(v4.z), d3 = dup2(v4.w);
            fma2(aL[n], d0, w[0].x); fma2(aH[n], d0, w[0].y);
            fma2(aL[n], d1, w[1].x); fma2(aH[n], d1, w[1].y);
            fma2(aL[n], d2, w[2].x); fma2(aH[n], d2, w[2].y);
            fma2(aL[n], d3, w[3].x); fma2(aH[n], d3, w[3].y);
        }
    }

    const float4 b2v = *reinterpret_cast<const float4*>(b2 + 4 * tc);
    float4* out4 = reinterpret_cast<float4*>(out);
    #pragma unroll
    for (int n = 0; n < 4; n++) {
        int gn = base + 4 * tn + n;
        if (gn < NN) {
            int d = g_deg[gn];
            float2 lo = unpack2(aL[n]), hi = unpack2(aH[n]);
            float4 o;
            if (d == 0) {
                o = make_float4(0.f, 0.f, 0.f, 0.f);
            } else {
                float inv = 1.0f / (float)d;
                o = make_float4(lo.x * inv + b2v.x, lo.y * inv + b2v.y,
                                hi.x * inv + b2v.z, hi.y * inv + b2v.w);
            }
            out4[gn * 16 + tc] = o;
        }
    }
}

// ---------------------------------------------------------------------------
// Launch
// ---------------------------------------------------------------------------
extern "C" void kernel_launch(void* const* d_in, const int* in_sizes, int n_in,
                              void* d_out, int out_size) {
    const float* x    = (const float*)d_in[0];
    const int*   eidx = (const int*)d_in[1];     // [2][E]: row then col
    const float* ea   = (const float*)d_in[2];
    const float* W1   = (const float*)d_in[3];
    const float* b1   = (const float*)d_in[4];
    const float* W2   = (const float*)d_in[5];
    const float* b2   = (const float*)d_in[6];
    float* out = (float*)d_out;

    const int* row = eidx;
    const int* col = eidx + EE;

    // 0) zero H + degrees
    {
        int total = (NN * OUT_C) / 4;
        zero_kernel<<<(total + 255) / 256, 256>>>();
    }
    // 0b) degree histogram
    hist_kernel<<<(EE + 255) / 256, 256>>>(col);
    // 1) per-node projections A, B
    pre_kernel<<<(NN + 63) / 64, 256>>>(x, W1);
    // 2) edge layer-1 + scatter h
    edge_kernel<<<1184, 256>>>(row, col, ea, W1, b1);
    // 3) node GEMM + mean + bias
    out_kernel<<<(NN + 63) / 64, 256>>>(W2, b2, out);
}

// round 7
// speedup vs baseline: 1.7789x; 1.0505x over previous
#include <cuda_runtime.h>
#include <cuda_bf16.h>
#include <cstdint>

// Problem constants (fixed shapes)
#define NN      50000
#define EE      800000
#define IN_C    64
#define EDGE_C  32
#define OUT_C   64
#define TILE_E  64
#define N_TILES (EE / TILE_E)   // 12500 exactly
#define CS_STRIDE 68            // padded C_s row stride (floats)

// Scratch (device globals; 16B-aligned for v4 access)
__device__ __align__(16) float g_A[NN * OUT_C];   // x @ W1[0:64]
__device__ __align__(16) float g_B[NN * OUT_C];   // x @ W1[64:128]
__device__ __align__(16) float g_H[NN * OUT_C];   // scatter-sum of relu(h)
__device__ int g_deg[NN];                          // in-degree

typedef unsigned long long u64;

// ---------------------------------------------------------------------------
// helpers
// ---------------------------------------------------------------------------
__device__ __forceinline__ u64 dup2(float v) {
    u64 r; asm("mov.b64 %0, {%1, %1};" : "=l"(r) : "f"(v)); return r;
}
__device__ __forceinline__ void fma2(u64& d, u64 a, u64 b) {
    asm("fma.rn.f32x2 %0, %1, %2, %0;" : "+l"(d) : "l"(a), "l"(b));
}
__device__ __forceinline__ float2 unpack2(u64 v) {
    float2 f; asm("mov.b64 {%0, %1}, %2;" : "=f"(f.x), "=f"(f.y) : "l"(v)); return f;
}
__device__ __forceinline__ void red_add_v4(float* p, float4 v) {
    asm volatile("red.global.add.v4.f32 [%0], {%1, %2, %3, %4};"
                 :: "l"(p), "f"(v.x), "f"(v.y), "f"(v.z), "f"(v.w)
                 : "memory");
}
__device__ __forceinline__ uint32_t f2tf32(float f) {
    uint32_t r; asm("cvt.rna.tf32.f32 %0, %1;" : "=r"(r) : "f"(f)); return r;
}
__device__ __forceinline__ void mma_tf32(float& c0, float& c1, float& c2, float& c3,
                                         uint32_t a0, uint32_t a1, uint32_t a2, uint32_t a3,
                                         uint32_t b0, uint32_t b1) {
    asm volatile(
        "mma.sync.aligned.m16n8k8.row.col.f32.tf32.tf32.f32 "
        "{%0,%1,%2,%3},{%4,%5,%6,%7},{%8,%9},{%0,%1,%2,%3};"
        : "+f"(c0), "+f"(c1), "+f"(c2), "+f"(c3)
        : "r"(a0), "r"(a1), "r"(a2), "r"(a3), "r"(b0), "r"(b1));
}

// ---------------------------------------------------------------------------
// Kernel 0: zero H accumulator + degrees
// ---------------------------------------------------------------------------
__global__ void zero_kernel() {
    int id = blockIdx.x * blockDim.x + threadIdx.x;
    if (id < (NN * OUT_C) / 4) {
        reinterpret_cast<float4*>(g_H)[id] = make_float4(0.f, 0.f, 0.f, 0.f);
    }
    if (id < NN) g_deg[id] = 0;
}

// ---------------------------------------------------------------------------
// Kernel 0b: degree histogram
// ---------------------------------------------------------------------------
__global__ void hist_kernel(const int* __restrict__ col) {
    int e = blockIdx.x * blockDim.x + threadIdx.x;
    if (e < EE) atomicAdd(&g_deg[col[e]], 1);
}

// ---------------------------------------------------------------------------
// Kernel 1: per-node precompute  A = x @ W1a,  B = x @ W1b  (fp32)
// ---------------------------------------------------------------------------
__global__ __launch_bounds__(256)
void pre_kernel(const float* __restrict__ x, const float* __restrict__ W1) {
    __shared__ __align__(16) float Wa_s[IN_C * OUT_C];
    __shared__ __align__(16) float Wb_s[IN_C * OUT_C];
    __shared__ __align__(16) float x_s[64 * IN_C];

    int t = threadIdx.x;
    for (int i = t; i < IN_C * OUT_C; i += 256) {
        Wa_s[i] = W1[i];
        Wb_s[i] = W1[IN_C * OUT_C + i];
    }

    const int tc = t & 15;
    const int tn = t >> 4;
    const int base = blockIdx.x * 64;
    {
        const float4* x4 = reinterpret_cast<const float4*>(x);
        float4* xs4 = reinterpret_cast<float4*>(x_s);
        #pragma unroll
        for (int i = 0; i < 4; i++) {
            int id = t + 256 * i;
            int n = id >> 4, q = id & 15;
            int gn = base + n;
            float4 v = make_float4(0.f, 0.f, 0.f, 0.f);
            if (gn < NN) v = x4[gn * 16 + q];
            xs4[n * 16 + q] = v;
        }
    }
    __syncthreads();

    u64 aAL[4], aAH[4], aBL[4], aBH[4];
    #pragma unroll
    for (int n = 0; n < 4; n++) { aAL[n] = 0; aAH[n] = 0; aBL[n] = 0; aBH[n] = 0; }

    const ulonglong2* wa2 = reinterpret_cast<const ulonglong2*>(Wa_s);
    const ulonglong2* wb2 = reinterpret_cast<const ulonglong2*>(Wb_s);
    const float4* xs4 = reinterpret_cast<const float4*>(x_s);

    #pragma unroll
    for (int kb = 0; kb < IN_C / 4; kb++) {
        ulonglong2 wa[4], wb[4];
        #pragma unroll
        for (int kk = 0; kk < 4; kk++) {
            wa[kk] = wa2[(4 * kb + kk) * 16 + tc];
            wb[kk] = wb2[(4 * kb + kk) * 16 + tc];
        }
        #pragma unroll
        for (int n = 0; n < 4; n++) {
            float4 v4 = xs4[(4 * tn + n) * 16 + kb];
            u64 d0 = dup2(v4.x), d1 = dup2(v4.y), d2 = dup2(v4.z), d3 = dup2(v4.w);
            fma2(aAL[n], d0, wa[0].x); fma2(aAH[n], d0, wa[0].y);
            fma2(aBL[n], d0, wb[0].x); fma2(aBH[n], d0, wb[0].y);
            fma2(aAL[n], d1, wa[1].x); fma2(aAH[n], d1, wa[1].y);
            fma2(aBL[n], d1, wb[1].x); fma2(aBH[n], d1, wb[1].y);
            fma2(aAL[n], d2, wa[2].x); fma2(aAH[n], d2, wa[2].y);
            fma2(aBL[n], d2, wb[2].x); fma2(aBH[n], d2, wb[2].y);
            fma2(aAL[n], d3, wa[3].x); fma2(aAH[n], d3, wa[3].y);
            fma2(aBL[n], d3, wb[3].x); fma2(aBH[n], d3, wb[3].y);
        }
    }

    float4* A4 = reinterpret_cast<float4*>(g_A);
    float4* B4 = reinterpret_cast<float4*>(g_B);
    #pragma unroll
    for (int n = 0; n < 4; n++) {
        int gn = base + 4 * tn + n;
        if (gn < NN) {
            float2 al = unpack2(aAL[n]), ah = unpack2(aAH[n]);
            float2 bl = unpack2(aBL[n]), bh = unpack2(aBH[n]);
            A4[gn * 16 + tc] = make_float4(al.x, al.y, ah.x, ah.y);
            B4[gn * 16 + tc] = make_float4(bl.x, bl.y, bh.x, bh.y);
        }
    }
}

// ---------------------------------------------------------------------------
// Kernel 2: edge kernel — tensor-core (tf32) ea@Wc + gather/relu/scatter.
// Tile = 64 edges. 8 warps: warp w handles edge-block eb=w>>1 (16 edges),
// channel half choff=(w&1)*32 (4 n-tiles of 8).
// Phase A: 16x m16n8k8.tf32 MMAs -> C_s[64][CS_STRIDE] (fp32 accum).
// Phase B: h = relu(A[row]+B[col]+C+b1); red.v4 into g_H[col].
// ---------------------------------------------------------------------------
__global__ __launch_bounds__(256)
void edge_kernel(const int* __restrict__ row, const int* __restrict__ col,
                 const float* __restrict__ ea,
                 const float* __restrict__ W1, const float* __restrict__ b1) {
    __shared__ __align__(16) float ea_f[4 * 4 * 128];       // [eb][ks][frag]  8KB
    __shared__ __align__(16) float C_s[TILE_E * CS_STRIDE]; // 17KB
    __shared__ int row_s[TILE_E];
    __shared__ int col_s[TILE_E];

    const int t = threadIdx.x;
    const int w = t >> 5;
    const int lane = t & 31;
    const int lr = lane >> 2;        // fragment groupID
    const int lk = lane & 3;         // fragment threadID-in-group
    const int eb = w >> 1;           // edge block (16 edges)
    const int choff = (w & 1) * 32;  // channel half

    // --- one-time: weight B-fragments (tf32) in registers ---
    const float* Wc = W1 + 128 * 64;               // W1 rows 128..159 = [32k][64c]
    uint32_t wb[4][4][2];                           // [nt][ks][2]
    #pragma unroll
    for (int nt = 0; nt < 4; nt++) {
        int c = choff + 8 * nt + lr;
        #pragma unroll
        for (int ks = 0; ks < 4; ks++) {
            wb[nt][ks][0] = f2tf32(Wc[(8 * ks + lk) * 64 + c]);
            wb[nt][ks][1] = f2tf32(Wc[(8 * ks + lk + 4) * 64 + c]);
        }
    }

    // --- phase-B constants ---
    const int tc = t & 7;            // 8 channels: 8*tc..8*tc+7
    const int teg = t >> 3;          // 0..31 -> edges 2*teg, 2*teg+1
    const float4 b1v0 = *reinterpret_cast<const float4*>(b1 + 8 * tc);
    const float4 b1v1 = *reinterpret_cast<const float4*>(b1 + 8 * tc + 4);
    const float4* A4 = reinterpret_cast<const float4*>(g_A);
    const float4* B4 = reinterpret_cast<const float4*>(g_B);
    const float4* eg4 = reinterpret_cast<const float4*>(ea);

    for (int tile = blockIdx.x; tile < N_TILES; tile += gridDim.x) {
        const int base = tile * TILE_E;

        __syncthreads();   // previous phase-B done reading C_s / idx
        // ---- stage indices + ea in A-fragment order ----
        if (t < TILE_E) { row_s[t] = row[base + t]; col_s[t] = col[base + t]; }
        {
            #pragma unroll
            for (int i = 0; i < 2; i++) {
                int id = t + 256 * i;            // 0..511 quads: e=id>>3, q=id&7
                int e = id >> 3, q = id & 7;
                float4 v = eg4[(size_t)base * 8 + id];
                int er = e & 15, ebb = e >> 4, ks = q >> 1;
                int ib = (er >> 3) | ((q & 1) << 1);
                float* dst = ea_f + (ebb * 4 + ks) * 128 + (er & 7) * 16;
                dst[ib]      = v.x;
                dst[4 + ib]  = v.y;
                dst[8 + ib]  = v.z;
                dst[12 + ib] = v.w;
            }
        }
        __syncthreads();

        // ---- phase A: MMA  C = ea @ Wc ----
        {
            float c0[4], c1[4], c2[4], c3[4];
            #pragma unroll
            for (int nt = 0; nt < 4; nt++) { c0[nt] = 0.f; c1[nt] = 0.f; c2[nt] = 0.f; c3[nt] = 0.f; }
            #pragma unroll
            for (int ks = 0; ks < 4; ks++) {
                float4 af = *reinterpret_cast<float4*>(ea_f + (eb * 4 + ks) * 128 + lane * 4);
                uint32_t a0 = f2tf32(af.x), a1 = f2tf32(af.y);
                uint32_t a2 = f2tf32(af.z), a3 = f2tf32(af.w);
                #pragma unroll
                for (int nt = 0; nt < 4; nt++)
                    mma_tf32(c0[nt], c1[nt], c2[nt], c3[nt],
                             a0, a1, a2, a3, wb[nt][ks][0], wb[nt][ks][1]);
            }
            // store C fragments to C_s
            #pragma unroll
            for (int nt = 0; nt < 4; nt++) {
                int ccol = choff + 8 * nt + 2 * lk;
                float2* p0 = reinterpret_cast<float2*>(C_s + (16 * eb + lr) * CS_STRIDE + ccol);
                float2* p1 = reinterpret_cast<float2*>(C_s + (16 * eb + lr + 8) * CS_STRIDE + ccol);
                *p0 = make_float2(c0[nt], c1[nt]);
                *p1 = make_float2(c2[nt], c3[nt]);
            }
        }
        __syncthreads();

        // ---- phase B: gather + add + relu + scatter ----
        #pragma unroll
        for (int e2 = 0; e2 < 2; e2++) {
            const int e = 2 * teg + e2;
            const int r = row_s[e], c = col_s[e];
            float4 a0 = A4[r * 16 + 2 * tc], a1 = A4[r * 16 + 2 * tc + 1];
            float4 g0 = B4[c * 16 + 2 * tc], g1 = B4[c * 16 + 2 * tc + 1];
            float4 m0 = *reinterpret_cast<float4*>(C_s + e * CS_STRIDE + 8 * tc);
            float4 m1 = *reinterpret_cast<float4*>(C_s + e * CS_STRIDE + 8 * tc + 4);
            float4 h0 = make_float4(
                fmaxf(a0.x + g0.x + m0.x + b1v0.x, 0.f),
                fmaxf(a0.y + g0.y + m0.y + b1v0.y, 0.f),
                fmaxf(a0.z + g0.z + m0.z + b1v0.z, 0.f),
                fmaxf(a0.w + g0.w + m0.w + b1v0.w, 0.f));
            float4 h1 = make_float4(
                fmaxf(a1.x + g1.x + m1.x + b1v1.x, 0.f),
                fmaxf(a1.y + g1.y + m1.y + b1v1.y, 0.f),
                fmaxf(a1.z + g1.z + m1.z + b1v1.z, 0.f),
                fmaxf(a1.w + g1.w + m1.w + b1v1.w, 0.f));
            red_add_v4(g_H + (size_t)c * OUT_C + 8 * tc, h0);
            red_add_v4(g_H + (size_t)c * OUT_C + 8 * tc + 4, h1);
        }
    }
}

// ---------------------------------------------------------------------------
// Kernel 3: node GEMM + mean + bias:  out = (H @ W2) / max(deg,1) + b2
// ---------------------------------------------------------------------------
__global__ __launch_bounds__(256)
void out_kernel(const float* __restrict__ W2, const float* __restrict__ b2,
                float* __restrict__ out) {
    __shared__ __align__(16) float W2_s[OUT_C * OUT_C];
    __shared__ __align__(16) float h_s[64 * OUT_C];

    const int t = threadIdx.x;
    for (int i = t; i < OUT_C * OUT_C; i += 256) W2_s[i] = W2[i];

    const int tc = t & 15;
    const int tn = t >> 4;
    const int base = blockIdx.x * 64;
    {
        const float4* H4 = reinterpret_cast<const float4*>(g_H);
        float4* hs4 = reinterpret_cast<float4*>(h_s);
        #pragma unroll
        for (int i = 0; i < 4; i++) {
            int id = t + 256 * i;
            int n = id >> 4, q = id & 15;
            int gn = base + n;
            float4 v = make_float4(0.f, 0.f, 0.f, 0.f);
            if (gn < NN) v = H4[gn * 16 + q];
            hs4[n * 16 + q] = v;
        }
    }
    __syncthreads();

    u64 aL[4], aH[4];
    #pragma unroll
    for (int n = 0; n < 4; n++) { aL[n] = 0; aH[n] = 0; }

    const ulonglong2* w2 = reinterpret_cast<const ulonglong2*>(W2_s);
    const float4* hs4 = reinterpret_cast<const float4*>(h_s);

    #pragma unroll
    for (int kb = 0; kb < OUT_C / 4; kb++) {
        ulonglong2 w[4];
        #pragma unroll
        for (int kk = 0; kk < 4; kk++) w[kk] = w2[(4 * kb + kk) * 16 + tc];
        #pragma unroll
        for (int n = 0; n < 4; n++) {
            float4 v4 = hs4[(4 * tn + n) * 16 + kb];
            u64 d0 = dup2(v4.x), d1 = dup2(v4.y), d2 = dup2(v4.z), d3 = dup2(v4.w);
            fma2(aL[n], d0, w[0].x); fma2(aH[n], d0, w[0].y);
            fma2(aL[n], d1, w[1].x); fma2(aH[n], d1, w[1].y);
            fma2(aL[n], d2, w[2].x); fma2(aH[n], d2, w[2].y);
            fma2(aL[n], d3, w[3].x); fma2(aH[n], d3, w[3].y);
        }
    }

    const float4 b2v = *reinterpret_cast<const float4*>(b2 + 4 * tc);
    float4* out4 = reinterpret_cast<float4*>(out);
    #pragma unroll
    for (int n = 0; n < 4; n++) {
        int gn = base + 4 * tn + n;
        if (gn < NN) {
            int d = g_deg[gn];
            float2 lo = unpack2(aL[n]), hi = unpack2(aH[n]);
            float4 o;
            if (d == 0) {
                o = make_float4(0.f, 0.f, 0.f, 0.f);
            } else {
                float inv = 1.0f / (float)d;
                o = make_float4(lo.x * inv + b2v.x, lo.y * inv + b2v.y,
                                hi.x * inv + b2v.z, hi.y * inv + b2v.w);
            }
            out4[gn * 16 + tc] = o;
        }
    }
}

// ---------------------------------------------------------------------------
// Launch
// ---------------------------------------------------------------------------
extern "C" void kernel_launch(void* const* d_in, const int* in_sizes, int n_in,
                              void* d_out, int out_size) {
    const float* x    = (const float*)d_in[0];
    const int*   eidx = (const int*)d_in[1];     // [2][E]: row then col
    const float* ea   = (const float*)d_in[2];
    const float* W1   = (const float*)d_in[3];
    const float* b1   = (const float*)d_in[4];
    const float* W2   = (const float*)d_in[5];
    const float* b2   = (const float*)d_in[6];
    float* out = (float*)d_out;

    const int* row = eidx;
    const int* col = eidx + EE;

    // 0) zero H + degrees
    {
        int total = (NN * OUT_C) / 4;
        zero_kernel<<<(total + 255) / 256, 256>>>();
    }
    // 0b) degree histogram
    hist_kernel<<<(EE + 255) / 256, 256>>>(col);
    // 1) per-node projections A, B
    pre_kernel<<<(NN + 63) / 64, 256>>>(x, W1);
    // 2) edge: tensor-core layer-1 + scatter h
    edge_kernel<<<1184, 256>>>(row, col, ea, W1, b1);
    // 3) node GEMM + mean + bias
    out_kernel<<<(NN + 63) / 64, 256>>>(W2, b2, out);
}